// round 7
// baseline (speedup 1.0000x reference)
#include <cuda_runtime.h>

// Fixed problem shape
#define BB   2048
#define TTN  2048
#define HH   51
#define RPB  16          // batch rows per block
#define NBLK 128
#define NTHR 256

typedef unsigned long long u64;

__device__ __forceinline__ u64 pk2(float a) {
    u64 r; asm("mov.b64 %0, {%1, %1};" : "=l"(r) : "f"(a)); return r;
}
__device__ __forceinline__ u64 fma2(u64 a, u64 b, u64 c) {
    u64 d; asm("fma.rn.f32x2 %0, %1, %2, %3;" : "=l"(d) : "l"(a), "l"(b), "l"(c)); return d;
}
union U2 { u64 v; float2 f; };

__device__ __forceinline__ float sigx(float x)  { return __fdividef(1.0f, 1.0f + __expf(-x)); }
__device__ __forceinline__ float tanhx(float x) { return __fdividef(2.0f, 1.0f + __expf(-2.0f * x)) - 1.0f; }

// ---------------- smem layout (float offsets) ----------------
// W1p : 102 rows x 27 float4   (gate-pair-interleaved, k-transposed; kp 0..25 data)
// W2p : 102 rows x 53 float4   (kp 0..51 data; zero w at km=51 (x slot) and km=103)
// gbufA/B : 4 gate-planes x 51 units x 20 floats (16 rows + pad 4)
// hcat2 : 8 rowpairs x 106 float2 (k: 0..50 h1, 51 x, 52..102 h2, 103..105 pad)
#define W1P_OFF 0                       // 102*27*4 = 11016
#define W2P_OFF 11016                   // 102*53*4 = 21624
#define GBA_OFF 32640                   // 4080
#define GBB_OFF 36720                   // 4080
#define HC_OFF  40800                   // 8*106*2 = 1696
#define BS1_OFF 42496                   // 208
#define BS2_OFF 42704                   // 208
#define WLS_OFF 42912                   // 52 + pad
#define SM_TOT  42968

__device__ __forceinline__ void gate_accum(const float4* __restrict__ wp,
                                           const float2* __restrict__ hb,   // hc2 + (rh*4)*106
                                           int kp0, int kp1, U2 acc[2][4]) {
    #pragma unroll 2
    for (int kp = kp0; kp < kp1; kp++) {
        float4 w4 = wp[kp];
        int km = kp << 1;
        ulonglong2 h0 = *reinterpret_cast<const ulonglong2*>(hb + 0 * 106 + km);
        ulonglong2 h1 = *reinterpret_cast<const ulonglong2*>(hb + 1 * 106 + km);
        ulonglong2 h2 = *reinterpret_cast<const ulonglong2*>(hb + 2 * 106 + km);
        ulonglong2 h3 = *reinterpret_cast<const ulonglong2*>(hb + 3 * 106 + km);
        u64 wa = pk2(w4.x), wb = pk2(w4.y), wc = pk2(w4.z), wd = pk2(w4.w);
        acc[0][0].v = fma2(wa, h0.x, acc[0][0].v);
        acc[0][1].v = fma2(wa, h1.x, acc[0][1].v);
        acc[0][2].v = fma2(wa, h2.x, acc[0][2].v);
        acc[0][3].v = fma2(wa, h3.x, acc[0][3].v);
        acc[1][0].v = fma2(wb, h0.x, acc[1][0].v);
        acc[1][1].v = fma2(wb, h1.x, acc[1][1].v);
        acc[1][2].v = fma2(wb, h2.x, acc[1][2].v);
        acc[1][3].v = fma2(wb, h3.x, acc[1][3].v);
        acc[0][0].v = fma2(wc, h0.y, acc[0][0].v);
        acc[0][1].v = fma2(wc, h1.y, acc[0][1].v);
        acc[0][2].v = fma2(wc, h2.y, acc[0][2].v);
        acc[0][3].v = fma2(wc, h3.y, acc[0][3].v);
        acc[1][0].v = fma2(wd, h0.y, acc[1][0].v);
        acc[1][1].v = fma2(wd, h1.y, acc[1][1].v);
        acc[1][2].v = fma2(wd, h2.y, acc[1][2].v);
        acc[1][3].v = fma2(wd, h3.y, acc[1][3].v);
    }
}

__device__ __forceinline__ void gbuf_store(float4* gb, int c2, int rh, U2 acc[2][4]) {
    int u = c2 >> 1, g0 = (c2 & 1) * 2;
    ulonglong2 t;
    t.x = acc[0][0].v; t.y = acc[0][1].v;
    *reinterpret_cast<ulonglong2*>(&gb[(g0 * 51 + u) * 5 + rh * 2])     = t;
    t.x = acc[0][2].v; t.y = acc[0][3].v;
    *reinterpret_cast<ulonglong2*>(&gb[(g0 * 51 + u) * 5 + rh * 2 + 1]) = t;
    t.x = acc[1][0].v; t.y = acc[1][1].v;
    *reinterpret_cast<ulonglong2*>(&gb[((g0 + 1) * 51 + u) * 5 + rh * 2])     = t;
    t.x = acc[1][2].v; t.y = acc[1][3].v;
    *reinterpret_cast<ulonglong2*>(&gb[((g0 + 1) * 51 + u) * 5 + rh * 2 + 1]) = t;
}

__device__ __forceinline__ float cellstep(float gi, float gf, float gg, float go, float& c) {
    float cn = sigx(gf) * c + sigx(gi) * tanhx(gg);
    c = cn;
    return sigx(go) * tanhx(cn);
}

__global__ __launch_bounds__(NTHR, 1)
void lstm2_kernel(const float* __restrict__ input,
                  const float* __restrict__ Wih1, const float* __restrict__ Whh1,
                  const float* __restrict__ bih1, const float* __restrict__ bhh1,
                  const float* __restrict__ Wih2, const float* __restrict__ Whh2,
                  const float* __restrict__ bih2, const float* __restrict__ bhh2,
                  const float* __restrict__ Wlin, const float* __restrict__ blin,
                  float* __restrict__ out)
{
    extern __shared__ float sm[];
    const int tid  = threadIdx.x;
    const int row0 = blockIdx.x * RPB;

    float4* W1p4 = reinterpret_cast<float4*>(sm + W1P_OFF);
    float4* W2p4 = reinterpret_cast<float4*>(sm + W2P_OFF);
    float4* gbA  = reinterpret_cast<float4*>(sm + GBA_OFF);
    float4* gbB  = reinterpret_cast<float4*>(sm + GBB_OFF);
    float2* hc2  = reinterpret_cast<float2*>(sm + HC_OFF);
    float*  bs1  = sm + BS1_OFF;
    float*  bs2  = sm + BS2_OFF;
    float*  wls  = sm + WLS_OFF;

    // ---------------- staging ----------------
    // W1p: float4 {w(g0,km), w(g1,km), w(g0,km+1), w(g1,km+1)}; km<51 -> Whh1, km==51 -> Wih1 (x)
    for (int q = tid; q < 102 * 27; q += NTHR) {
        int c2i = q / 27, kp = q % 27;
        int u = c2i >> 1, g0 = (c2i & 1) * 2;
        float4 v = make_float4(0.f, 0.f, 0.f, 0.f);
        if (kp < 26) {
            int km0 = 2 * kp, km1 = km0 + 1;
            int r0 = g0 * HH + u, r1 = (g0 + 1) * HH + u;
            v.x = (km0 < HH) ? Whh1[r0 * HH + km0] : Wih1[r0];
            v.y = (km0 < HH) ? Whh1[r1 * HH + km0] : Wih1[r1];
            v.z = (km1 < HH) ? Whh1[r0 * HH + km1] : Wih1[r0];
            v.w = (km1 < HH) ? Whh1[r1 * HH + km1] : Wih1[r1];
        }
        W1p4[q] = v;
    }
    // W2p: km<51 -> Wih2 (acting on h1), km==51 -> 0 (x slot), 52..102 -> Whh2, 103 -> 0
    for (int q = tid; q < 102 * 53; q += NTHR) {
        int c2i = q / 53, kp = q % 53;
        int u = c2i >> 1, g0 = (c2i & 1) * 2;
        float4 v = make_float4(0.f, 0.f, 0.f, 0.f);
        if (kp < 52) {
            int r0 = g0 * HH + u, r1 = (g0 + 1) * HH + u;
            int km0 = 2 * kp, km1 = km0 + 1;
            #define W2VAL(r, km) ((km) < HH ? Wih2[(r) * HH + (km)] : \
                                  ((km) == HH ? 0.0f : ((km) <= 102 ? Whh2[(r) * HH + ((km) - 52)] : 0.0f)))
            v.x = W2VAL(r0, km0); v.y = W2VAL(r1, km0);
            v.z = W2VAL(r0, km1); v.w = W2VAL(r1, km1);
            #undef W2VAL
        }
        W2p4[q] = v;
    }
    for (int c = tid; c < 208; c += NTHR) {
        if (c < 204) {
            int u = c >> 2, g = c & 3, j = g * HH + u;
            bs1[c] = bih1[j] + bhh1[j];
            bs2[c] = bih2[j] + bhh2[j];
        } else { bs1[c] = 0.f; bs2[c] = 0.f; }
    }
    if (tid < HH) wls[tid] = Wlin[tid];
    for (int i = tid; i < 8 * 106 * 2; i += NTHR) ((float*)hc2)[i] = 0.f;
    __syncthreads();
    // x_0 into slot km=51
    if (tid < 8)
        hc2[tid * 106 + 51] = make_float2(input[(row0 + 2 * tid) * TTN],
                                          input[(row0 + 2 * tid + 1) * TTN]);
    __syncthreads();

    // ---------------- roles ----------------
    const bool cw = (tid < 204);
    const int  c2 = tid >> 1, rh = tid & 1;       // gate coords
    const int  au = tid % HH, arg = tid / HH;     // act coords (valid for tid<204)
    const bool yw = (tid >= 224 && tid < 240);
    const int  yr = tid - 224;
    const bool xw = (tid >= 240 && tid < 248);
    const int  xp = tid - 240;

    const float4* w1p = W1p4 + c2 * 27;
    const float4* w2p = W2p4 + c2 * 53;
    const float2* hb  = hc2 + (rh * 4) * 106;     // gate-thread row base

    float c1s[4] = {0.f, 0.f, 0.f, 0.f};
    float c2s[4] = {0.f, 0.f, 0.f, 0.f};
    U2 acc[2][4];
    const float ybias = blin[0];

    float2 xa = make_float2(0.f, 0.f);            // x_{t+1} pipeline regs
    if (xw) xa = make_float2(input[(row0 + 2 * xp) * TTN + 1],
                             input[(row0 + 2 * xp + 1) * TTN + 1]);

    // ---------------- prolog: L1 gates for t=0 -> gbufA ----------------
    if (cw) {
        float b0 = bs1[2 * c2], b1 = bs1[2 * c2 + 1];
        acc[0][0].v = acc[0][1].v = acc[0][2].v = acc[0][3].v = pk2(b0);
        acc[1][0].v = acc[1][1].v = acc[1][2].v = acc[1][3].v = pk2(b1);
        gate_accum(w1p, hb, 0, 26, acc);
        gbuf_store(gbA, c2, rh, acc);
    }
    __syncthreads();

    // ---------------- main loop: 3 barriers/step ----------------
    for (int t = 0; t < TTN; t++) {
        // === P1: act1 (gbufA) + write h1 + L2 partial over old h2 ===
        if (cw) {
            float4 gi = gbA[(0 * 51 + au) * 5 + arg];
            float4 gf = gbA[(1 * 51 + au) * 5 + arg];
            float4 gG = gbA[(2 * 51 + au) * 5 + arg];
            float4 go = gbA[(3 * 51 + au) * 5 + arg];
            float h0 = cellstep(gi.x, gf.x, gG.x, go.x, c1s[0]);
            float h1 = cellstep(gi.y, gf.y, gG.y, go.y, c1s[1]);
            float h2 = cellstep(gi.z, gf.z, gG.z, go.z, c1s[2]);
            float h3 = cellstep(gi.w, gf.w, gG.w, go.w, c1s[3]);
            hc2[(2 * arg) * 106 + au]     = make_float2(h0, h1);
            hc2[(2 * arg + 1) * 106 + au] = make_float2(h2, h3);
            float b0 = bs2[2 * c2], b1 = bs2[2 * c2 + 1];
            acc[0][0].v = acc[0][1].v = acc[0][2].v = acc[0][3].v = pk2(b0);
            acc[1][0].v = acc[1][1].v = acc[1][2].v = acc[1][3].v = pk2(b1);
            gate_accum(w2p, hb, 26, 52, acc);   // km 52..103: old h2 (+ zero pad)
        } else if (yw && t > 0) {
            // y_{t-1} from old h2 (stable until P3)
            const float* h2f = reinterpret_cast<const float*>(hc2);
            int base = ((yr >> 1) * 106 + 52) * 2 + (yr & 1);
            float y = ybias;
            #pragma unroll 3
            for (int u = 0; u < HH; u++) y += h2f[base + 2 * u] * wls[u];
            out[(row0 + yr) * TTN + (t - 1)] = y;
        }
        __syncthreads();

        // === P2: L2 rest over new h1 (+x slot, zero weight) -> gbufB ===
        if (cw) {
            gate_accum(w2p, hb, 0, 26, acc);    // km 0..51
            gbuf_store(gbB, c2, rh, acc);
        } else if (xw) {
            hc2[xp * 106 + 51] = xa;            // publish x_{t+1}
            if (t + 2 < TTN)
                xa = make_float2(input[(row0 + 2 * xp) * TTN + t + 2],
                                 input[(row0 + 2 * xp + 1) * TTN + t + 2]);
        }
        __syncthreads();

        // === P3: act2 (gbufB) + write h2 + L1 gates for t+1 -> gbufA ===
        if (cw) {
            float4 gi = gbB[(0 * 51 + au) * 5 + arg];
            float4 gf = gbB[(1 * 51 + au) * 5 + arg];
            float4 gG = gbB[(2 * 51 + au) * 5 + arg];
            float4 go = gbB[(3 * 51 + au) * 5 + arg];
            float h0 = cellstep(gi.x, gf.x, gG.x, go.x, c2s[0]);
            float h1 = cellstep(gi.y, gf.y, gG.y, go.y, c2s[1]);
            float h2 = cellstep(gi.z, gf.z, gG.z, go.z, c2s[2]);
            float h3 = cellstep(gi.w, gf.w, gG.w, go.w, c2s[3]);
            hc2[(2 * arg) * 106 + 52 + au]     = make_float2(h0, h1);
            hc2[(2 * arg + 1) * 106 + 52 + au] = make_float2(h2, h3);
            float b0 = bs1[2 * c2], b1 = bs1[2 * c2 + 1];
            acc[0][0].v = acc[0][1].v = acc[0][2].v = acc[0][3].v = pk2(b0);
            acc[1][0].v = acc[1][1].v = acc[1][2].v = acc[1][3].v = pk2(b1);
            gate_accum(w1p, hb, 0, 26, acc);    // reads h1_t + x_{t+1}
            gbuf_store(gbA, c2, rh, acc);
        }
        __syncthreads();
    }

    // epilog: y_{T-1}
    if (yw) {
        const float* h2f = reinterpret_cast<const float*>(hc2);
        int base = ((yr >> 1) * 106 + 52) * 2 + (yr & 1);
        float y = ybias;
        #pragma unroll 3
        for (int u = 0; u < HH; u++) y += h2f[base + 2 * u] * wls[u];
        out[(row0 + yr) * TTN + (TTN - 1)] = y;
    }
}

extern "C" void kernel_launch(void* const* d_in, const int* in_sizes, int n_in,
                              void* d_out, int out_size) {
    const float* input = (const float*)d_in[0];
    const float* Wih1  = (const float*)d_in[1];
    const float* Whh1  = (const float*)d_in[2];
    const float* bih1  = (const float*)d_in[3];
    const float* bhh1  = (const float*)d_in[4];
    const float* Wih2  = (const float*)d_in[5];
    const float* Whh2  = (const float*)d_in[6];
    const float* bih2  = (const float*)d_in[7];
    const float* bhh2  = (const float*)d_in[8];
    const float* Wlin  = (const float*)d_in[9];
    const float* blin  = (const float*)d_in[10];
    float* out = (float*)d_out;

    const size_t smem = SM_TOT * sizeof(float);   // ~172 KB
    cudaFuncSetAttribute(lstm2_kernel, cudaFuncAttributeMaxDynamicSharedMemorySize, (int)smem);

    lstm2_kernel<<<NBLK, NTHR, smem>>>(input, Wih1, Whh1, bih1, bhh1,
                                       Wih2, Whh2, bih2, bhh2, Wlin, blin, out);
}